// round 10
// baseline (speedup 1.0000x reference)
#include <cuda_runtime.h>
#include <cstdint>

// Problem constants
#define BSZ   4
#define CSQ   1024
#define PSQ   1024
#define DIN   1024
#define NH    16
#define HDIM  64
#define TT    2048        // T = CS + PS
#define LQG   4096        // BSZ*CSQ global query rows
#define HD    1024        // NH*HDIM
#define SCALE 0.125f      // 1/sqrt(64)

// ---------------------------------------------------------------------------
// Scratch (device globals; no dynamic allocation allowed)
// ---------------------------------------------------------------------------
__device__ float g_qv[(size_t)LQG * HD];                 //  16.8 MB  tf32r(q + v)
__device__ float g_qu[(size_t)LQG * HD];                 //  16.8 MB  tf32r(q + u)
__device__ float g_kv[(size_t)BSZ * TT * 2 * HD];        //  67 MB    [k | v] (tf32)
__device__ float g_p [(size_t)TT * HD];                  //   8.4 MB  p_tfmd (tf32)
__device__ float g_P [(size_t)NH * LQG * TT];            // 512 MB    pos scores (fp32)
__device__ float g_ao[(size_t)LQG * HD];                 //  16.8 MB  attn out (tf32)
// tf32-converted external operands
__device__ float c_in  [(size_t)BSZ * CSQ * DIN];        //  16.8 MB
__device__ float c_mem [(size_t)BSZ * PSQ * DIN];        //  16.8 MB
__device__ float c_pos [(size_t)TT * DIN];               //   8.4 MB
__device__ float c_Wkv [(size_t)DIN * 2 * HD];           //   8.4 MB
__device__ float c_Wq  [(size_t)DIN * HD];               //   4.2 MB
__device__ float c_Wp  [(size_t)DIN * HD];               //   4.2 MB
__device__ float c_Wout[(size_t)HD * DIN];               //   4.2 MB

// ---------------------------------------------------------------------------
// tf32 / mma / cp.async helpers
// ---------------------------------------------------------------------------
__device__ __forceinline__ float tf32r(float x) {
    float y;
    asm("cvt.rna.tf32.f32 %0, %1;" : "=f"(y) : "f"(x));
    return y;
}

__global__ void __launch_bounds__(256) cvt_tf32_k(const float* __restrict__ in,
                                                  float* __restrict__ out, int n4)
{
    int i = blockIdx.x * 256 + threadIdx.x;
    if (i < n4) {
        float4 v = ((const float4*)in)[i];
        ((float4*)out)[i] = make_float4(tf32r(v.x), tf32r(v.y), tf32r(v.z), tf32r(v.w));
    }
}

// D += A(16x8 row) * B(8x8 col)
__device__ __forceinline__ void mma8(float* d, const float* a, const float* b) {
    asm volatile(
        "mma.sync.aligned.m16n8k8.row.col.f32.tf32.tf32.f32 "
        "{%0,%1,%2,%3}, {%4,%5,%6,%7}, {%8,%9}, {%0,%1,%2,%3};"
        : "+f"(d[0]), "+f"(d[1]), "+f"(d[2]), "+f"(d[3])
        : "r"(__float_as_uint(a[0])), "r"(__float_as_uint(a[1])),
          "r"(__float_as_uint(a[2])), "r"(__float_as_uint(a[3])),
          "r"(__float_as_uint(b[0])), "r"(__float_as_uint(b[1])));
}

__device__ __forceinline__ uint32_t smem_u32(const void* p) {
    return (uint32_t)__cvta_generic_to_shared(p);
}
#define CPA16(dst, src) \
    asm volatile("cp.async.cg.shared.global [%0], [%1], 16;" :: "r"(dst), "l"(src))
#define CPA_COMMIT() asm volatile("cp.async.commit_group;")
#define CPA_WAIT(n)  asm volatile("cp.async.wait_group %0;" :: "n"(n))
#define CPA_WAIT_TAIL(rem) do {                         \
        if ((rem) >= 2)      CPA_WAIT(2);               \
        else if ((rem) == 1) CPA_WAIT(1);               \
        else                 CPA_WAIT(0);               \
    } while (0)

// ---------------------------------------------------------------------------
// Generic 128x128 tf32 GEMM on PRE-CONVERTED tf32 inputs.
// MODE 0: A plain. MODE 1: A rows = virtual concat(memory, input_).
// EPI 0: plain store. EPI 1: tf32r store. EPI 2: dual store
//        C = tf32r(acc + Vb[col]), C2 = tf32r(acc + Ub[col]).
// 128 threads = 4 warps 2(m)x2(n); warp tile 64x64; 4-stage cp.async.
// ---------------------------------------------------------------------------
#define GEMM_SMEM ((4 * (128 * 20) + 4 * (16 * 136)) * 4)

template <int MODE, int EPI>
__global__ void __launch_bounds__(128) gemm_tf32(
    const float* __restrict__ A, const float* __restrict__ A2,
    const float* __restrict__ B, float* __restrict__ C,
    float* __restrict__ C2, const float* __restrict__ Vb,
    const float* __restrict__ Ub,
    int M, int N, int K)
{
    extern __shared__ float sm[];
    float (*As)[128][20] = reinterpret_cast<float(*)[128][20]>(sm);
    float (*Bs)[16][136] = reinterpret_cast<float(*)[16][136]>(sm + 4 * 128 * 20);

    const int tid  = threadIdx.x;
    const int lane = tid & 31;
    const int w    = tid >> 5;
    const int wm   = (w >> 1) * 64;
    const int wn   = (w & 1) * 64;
    const int bm   = blockIdx.y * 128;
    const int bn   = blockIdx.x * 128;
    const int ms   = lane >> 2;
    const int kb   = lane & 3;

    const float* arow;
    if (MODE == 0) {
        arow = A + (size_t)(bm + tid) * K;
    } else {
        int row = bm + tid;
        int b   = row / TT;
        int r   = row - b * TT;
        arow = (r < PSQ) ? A  + (size_t)(b * PSQ + r)         * K
                         : A2 + (size_t)(b * CSQ + (r - PSQ)) * K;
    }

    auto issue = [&](int s, int k0) {
        uint32_t ad = smem_u32(&As[s][tid][0]);
        CPA16(ad,      arow + k0);
        CPA16(ad + 16, arow + k0 + 4);
        CPA16(ad + 32, arow + k0 + 8);
        CPA16(ad + 48, arow + k0 + 12);
#pragma unroll
        for (int i = 0; i < 4; i++) {
            int id = tid + 128 * i;
            int kR = id >> 5;
            int ch = id & 31;
            CPA16(smem_u32(&Bs[s][kR][ch * 4]),
                  B + (size_t)(k0 + kR) * N + bn + ch * 4);
        }
        CPA_COMMIT();
    };

    const int T = K / 16;
    issue(0, 0); issue(1, 16); issue(2, 32);

    float acc[4][8][4] = {};

    for (int t = 0; t < T; t++) {
        CPA_WAIT_TAIL(T - 1 - t);
        __syncthreads();
        if (t + 3 < T) issue((t + 3) & 3, (t + 3) * 16);
        const int s = t & 3;
#pragma unroll
        for (int kk = 0; kk < 16; kk += 8) {
            const int kr = kk + kb;
            float a[4][4], b[8][2];
#pragma unroll
            for (int mt = 0; mt < 4; mt++) {
                a[mt][0] = As[s][wm + mt * 16 + ms][kr];
                a[mt][1] = As[s][wm + mt * 16 + ms + 8][kr];
                a[mt][2] = As[s][wm + mt * 16 + ms][kr + 4];
                a[mt][3] = As[s][wm + mt * 16 + ms + 8][kr + 4];
            }
#pragma unroll
            for (int nt = 0; nt < 8; nt++) {
                b[nt][0] = Bs[s][kr][wn + nt * 8 + ms];
                b[nt][1] = Bs[s][kr + 4][wn + nt * 8 + ms];
            }
#pragma unroll
            for (int mt = 0; mt < 4; mt++)
#pragma unroll
                for (int nt = 0; nt < 8; nt++)
                    mma8(acc[mt][nt], a[mt], b[nt]);
        }
    }

#pragma unroll
    for (int mt = 0; mt < 4; mt++) {
        int r0 = bm + wm + mt * 16 + ms;
#pragma unroll
        for (int nt = 0; nt < 8; nt++) {
            int c0 = bn + wn + nt * 8 + kb * 2;
            if (EPI == 0) {
                *(float2*)&C[(size_t)r0 * N + c0]       = make_float2(acc[mt][nt][0], acc[mt][nt][1]);
                *(float2*)&C[(size_t)(r0 + 8) * N + c0] = make_float2(acc[mt][nt][2], acc[mt][nt][3]);
            } else if (EPI == 1) {
                *(float2*)&C[(size_t)r0 * N + c0]       = make_float2(tf32r(acc[mt][nt][0]), tf32r(acc[mt][nt][1]));
                *(float2*)&C[(size_t)(r0 + 8) * N + c0] = make_float2(tf32r(acc[mt][nt][2]), tf32r(acc[mt][nt][3]));
            } else {
                float v0 = Vb[c0], v1 = Vb[c0 + 1];
                float u0 = Ub[c0], u1 = Ub[c0 + 1];
                *(float2*)&C[(size_t)r0 * N + c0]        = make_float2(tf32r(acc[mt][nt][0] + v0), tf32r(acc[mt][nt][1] + v1));
                *(float2*)&C[(size_t)(r0 + 8) * N + c0]  = make_float2(tf32r(acc[mt][nt][2] + v0), tf32r(acc[mt][nt][3] + v1));
                *(float2*)&C2[(size_t)r0 * N + c0]       = make_float2(tf32r(acc[mt][nt][0] + u0), tf32r(acc[mt][nt][1] + u1));
                *(float2*)&C2[(size_t)(r0 + 8) * N + c0] = make_float2(tf32r(acc[mt][nt][2] + u0), tf32r(acc[mt][nt][3] + u1));
            }
        }
    }
}

// ---------------------------------------------------------------------------
// P[h][L][jj] = sum_d qv[L,h,d] * p[jj,h,d]   (NT, K=64), inputs pre-tf32.
// 4-stage cp.async; both tiles staged [row][k] pitch 20.
// ---------------------------------------------------------------------------
#define POS_SMEM (2 * 4 * 128 * 20 * 4)

__global__ void __launch_bounds__(128) pos_gemm_tf32(
    const float* __restrict__ qv, const float* __restrict__ p,
    float* __restrict__ P)
{
    extern __shared__ float sm[];
    float (*As)[128][20] = reinterpret_cast<float(*)[128][20]>(sm);
    float (*Bs)[128][20] = reinterpret_cast<float(*)[128][20]>(sm + 4 * 128 * 20);

    const int tid  = threadIdx.x;
    const int lane = tid & 31;
    const int w    = tid >> 5;
    const int wm   = (w >> 1) * 64;
    const int wn   = (w & 1) * 64;
    const int h    = blockIdx.z;
    const int L0   = blockIdx.y * 128;
    const int j0   = blockIdx.x * 128;
    const int ms   = lane >> 2;
    const int kb   = lane & 3;

    const float* arow = qv + (size_t)(L0 + tid) * HD + h * HDIM;
    const float* brow = p  + (size_t)(j0 + tid) * HD + h * HDIM;

    auto issue = [&](int s, int k0) {
        uint32_t ad = smem_u32(&As[s][tid][0]);
        CPA16(ad,      arow + k0);
        CPA16(ad + 16, arow + k0 + 4);
        CPA16(ad + 32, arow + k0 + 8);
        CPA16(ad + 48, arow + k0 + 12);
        uint32_t bd = smem_u32(&Bs[s][tid][0]);
        CPA16(bd,      brow + k0);
        CPA16(bd + 16, brow + k0 + 4);
        CPA16(bd + 32, brow + k0 + 8);
        CPA16(bd + 48, brow + k0 + 12);
        CPA_COMMIT();
    };

    const int T = 4;   // HDIM / 16
    issue(0, 0); issue(1, 16); issue(2, 32);

    float acc[4][8][4] = {};

#pragma unroll
    for (int t = 0; t < T; t++) {
        CPA_WAIT_TAIL(T - 1 - t);
        __syncthreads();
        if (t + 3 < T) issue((t + 3) & 3, (t + 3) * 16);
        const int s = t & 3;
#pragma unroll
        for (int kk = 0; kk < 16; kk += 8) {
            const int kr = kk + kb;
            float a[4][4], b[8][2];
#pragma unroll
            for (int mt = 0; mt < 4; mt++) {
                a[mt][0] = As[s][wm + mt * 16 + ms][kr];
                a[mt][1] = As[s][wm + mt * 16 + ms + 8][kr];
                a[mt][2] = As[s][wm + mt * 16 + ms][kr + 4];
                a[mt][3] = As[s][wm + mt * 16 + ms + 8][kr + 4];
            }
#pragma unroll
            for (int nt = 0; nt < 8; nt++) {
                b[nt][0] = Bs[s][wn + nt * 8 + ms][kr];
                b[nt][1] = Bs[s][wn + nt * 8 + ms][kr + 4];
            }
#pragma unroll
            for (int mt = 0; mt < 4; mt++)
#pragma unroll
                for (int nt = 0; nt < 8; nt++)
                    mma8(acc[mt][nt], a[mt], b[nt]);
        }
    }

#pragma unroll
    for (int mt = 0; mt < 4; mt++) {
        int r0 = L0 + wm + mt * 16 + ms;
#pragma unroll
        for (int nt = 0; nt < 8; nt++) {
            int c0 = j0 + wn + nt * 8 + kb * 2;
            float* o = P + ((size_t)h * LQG + r0) * TT + c0;
            *(float2*)o            = make_float2(acc[mt][nt][0], acc[mt][nt][1]);
            *(float2*)(o + 8 * TT) = make_float2(acc[mt][nt][2], acc[mt][nt][3]);
        }
    }
}

// ---------------------------------------------------------------------------
// rel_shift gather: pos(b,i,j) with L = b*CS+i
// ---------------------------------------------------------------------------
__device__ __forceinline__ float pos_val(const float* __restrict__ Pm,
                                         int h, int L, int jj)
{
    int s  = jj + LQG - L;
    int n  = (s > TT) + (s > 2 * TT + 1);
    int jp = s - n * (TT + 1);
    int Lp = L + n;
    float pos = 0.f;
    if (jp > 0 && Lp < LQG)
        pos = Pm[((size_t)h * LQG + Lp) * TT + (jp - 1)];
    return pos;
}

// ---------------------------------------------------------------------------
// Fused attention on pre-tf32 inputs: qu already biased+rounded; kv rounded.
// ao stores tf32-rounded (feeds the out-GEMM).
// ---------------------------------------------------------------------------
#define ATT_SMEM ((64 * 136 + 64 * 72 + 64 * 72) * 4)

__global__ void __launch_bounds__(256) attn_fused(
    const float* __restrict__ qu, const float* __restrict__ kv,
    const float* __restrict__ Pm, float* __restrict__ ao)
{
    extern __shared__ float dyn[];
    float (*Sp)[136] = (float(*)[136])dyn;
    float (*Bk)[72]  = (float(*)[72])(dyn + 64 * 136);
    float (*Bv)[72]  = (float(*)[72])(dyn + 64 * 136 + 64 * 72);

    const int tid  = threadIdx.x;
    const int lane = tid & 31;
    const int w    = tid >> 5;
    const int wm   = w * 16;
    const int bh   = blockIdx.y;
    const int b    = bh >> 4;
    const int h    = bh & 15;
    const int i0   = blockIdx.x * 128;
    const int r    = lane >> 2;
    const int kb   = lane & 3;

    {
        int row = tid >> 1;
        int kq  = (tid & 1) * 32;
        const float* qr = qu + (size_t)(b * CSQ + i0 + row) * HD + h * HDIM + kq;
#pragma unroll
        for (int i = 0; i < 8; i++) {
            float4 a = *(const float4*)(qr + i * 4);
            Sp[kq + i * 4 + 0][row] = a.x;
            Sp[kq + i * 4 + 1][row] = a.y;
            Sp[kq + i * 4 + 2][row] = a.z;
            Sp[kq + i * 4 + 3][row] = a.w;
        }
    }
    __syncthreads();
    float aq[8][4];
#pragma unroll
    for (int ks = 0; ks < 8; ks++) {
        aq[ks][0] = Sp[ks * 8 + kb][wm + r];
        aq[ks][1] = Sp[ks * 8 + kb][wm + r + 8];
        aq[ks][2] = Sp[ks * 8 + kb + 4][wm + r];
        aq[ks][3] = Sp[ks * 8 + kb + 4][wm + r + 8];
    }
    __syncthreads();

    float m0 = -3.0e38f, m1 = -3.0e38f, l0 = 0.f, l1 = 0.f;
    float acc_o[8][4] = {};

    const int row0 = i0 + wm + r;
    const int Lr   = b * CSQ + row0;
    const int Kef  = min(TT, i0 + 128 + PSQ);

    for (int j0 = 0; j0 < Kef; j0 += 64) {
        {
            int j  = tid & 63;
            int dq = (tid >> 6) * 16;
            const float* kr_ = kv + ((size_t)(b * TT + j0 + j)) * (2 * HD) + h * HDIM + dq;
#pragma unroll
            for (int i = 0; i < 4; i++) {
                float4 kx = *(const float4*)(kr_ + i * 4);
                Bk[dq + i * 4 + 0][j] = kx.x;
                Bk[dq + i * 4 + 1][j] = kx.y;
                Bk[dq + i * 4 + 2][j] = kx.z;
                Bk[dq + i * 4 + 3][j] = kx.w;
            }
            const float* vr_ = kr_ + HD;
#pragma unroll
            for (int i = 0; i < 4; i++)
                *(float4*)&Bv[j][dq + i * 4] = *(const float4*)(vr_ + i * 4);
        }
        __syncthreads();

        float s[8][4] = {};
#pragma unroll
        for (int ks = 0; ks < 8; ks++) {
            float bq[8][2];
#pragma unroll
            for (int nt = 0; nt < 8; nt++) {
                bq[nt][0] = Bk[ks * 8 + kb][nt * 8 + r];
                bq[nt][1] = Bk[ks * 8 + kb + 4][nt * 8 + r];
            }
#pragma unroll
            for (int nt = 0; nt < 8; nt++)
                mma8(s[nt], aq[ks], bq[nt]);
        }

#pragma unroll
        for (int nt = 0; nt < 8; nt++) {
            int jjb = j0 + nt * 8 + 2 * kb;
#pragma unroll
            for (int cc = 0; cc < 2; cc++) {
                int jj = jjb + cc;
                s[nt][cc]     = (jj > row0 + PSQ)     ? -1e30f
                              : (s[nt][cc]     + pos_val(Pm, h, Lr, jj))     * SCALE;
                s[nt][2 + cc] = (jj > row0 + 8 + PSQ) ? -1e30f
                              : (s[nt][2 + cc] + pos_val(Pm, h, Lr + 8, jj)) * SCALE;
            }
        }

        float tm0 = -3.0e38f, tm1 = -3.0e38f;
#pragma unroll
        for (int nt = 0; nt < 8; nt++) {
            tm0 = fmaxf(tm0, fmaxf(s[nt][0], s[nt][1]));
            tm1 = fmaxf(tm1, fmaxf(s[nt][2], s[nt][3]));
        }
        tm0 = fmaxf(tm0, __shfl_xor_sync(0xffffffffu, tm0, 1));
        tm0 = fmaxf(tm0, __shfl_xor_sync(0xffffffffu, tm0, 2));
        tm1 = fmaxf(tm1, __shfl_xor_sync(0xffffffffu, tm1, 1));
        tm1 = fmaxf(tm1, __shfl_xor_sync(0xffffffffu, tm1, 2));
        float mn0 = fmaxf(m0, tm0), mn1 = fmaxf(m1, tm1);
        float f0 = __expf(m0 - mn0), f1 = __expf(m1 - mn1);

        float ps0 = 0.f, ps1 = 0.f;
#pragma unroll
        for (int nt = 0; nt < 8; nt++) {
            s[nt][0] = __expf(s[nt][0] - mn0);
            s[nt][1] = __expf(s[nt][1] - mn0);
            s[nt][2] = __expf(s[nt][2] - mn1);
            s[nt][3] = __expf(s[nt][3] - mn1);
            ps0 += s[nt][0] + s[nt][1];
            ps1 += s[nt][2] + s[nt][3];
        }
        ps0 += __shfl_xor_sync(0xffffffffu, ps0, 1);
        ps0 += __shfl_xor_sync(0xffffffffu, ps0, 2);
        ps1 += __shfl_xor_sync(0xffffffffu, ps1, 1);
        ps1 += __shfl_xor_sync(0xffffffffu, ps1, 2);
        l0 = l0 * f0 + ps0;
        l1 = l1 * f1 + ps1;
        m0 = mn0; m1 = mn1;

#pragma unroll
        for (int nt = 0; nt < 8; nt++) {
            acc_o[nt][0] *= f0; acc_o[nt][1] *= f0;
            acc_o[nt][2] *= f1; acc_o[nt][3] *= f1;
        }

#pragma unroll
        for (int nt = 0; nt < 8; nt++) {
            int jl = nt * 8 + 2 * kb;
            Sp[jl    ][wm + r]     = tf32r(s[nt][0]);
            Sp[jl + 1][wm + r]     = tf32r(s[nt][1]);
            Sp[jl    ][wm + r + 8] = tf32r(s[nt][2]);
            Sp[jl + 1][wm + r + 8] = tf32r(s[nt][3]);
        }
        __syncwarp();

#pragma unroll
        for (int kj = 0; kj < 8; kj++) {
            float a[4];
            a[0] = Sp[kj * 8 + kb][wm + r];
            a[1] = Sp[kj * 8 + kb][wm + r + 8];
            a[2] = Sp[kj * 8 + kb + 4][wm + r];
            a[3] = Sp[kj * 8 + kb + 4][wm + r + 8];
            float bq[8][2];
#pragma unroll
            for (int nt = 0; nt < 8; nt++) {
                bq[nt][0] = Bv[kj * 8 + kb][nt * 8 + r];
                bq[nt][1] = Bv[kj * 8 + kb + 4][nt * 8 + r];
            }
#pragma unroll
            for (int nt = 0; nt < 8; nt++)
                mma8(acc_o[nt], a, bq[nt]);
        }
        __syncthreads();
    }

    float inv0 = 1.0f / l0, inv1 = 1.0f / l1;
#pragma unroll
    for (int nt = 0; nt < 8; nt++) {
        int c0 = nt * 8 + 2 * kb;
        float* o0 = ao + (size_t)(b * CSQ + row0) * HD + h * HDIM + c0;
        *(float2*)o0            = make_float2(tf32r(acc_o[nt][0] * inv0), tf32r(acc_o[nt][1] * inv0));
        *(float2*)(o0 + 8 * HD) = make_float2(tf32r(acc_o[nt][2] * inv1), tf32r(acc_o[nt][3] * inv1));
    }
}

// ---------------------------------------------------------------------------
// Launch. Inputs: input_, pos_embs, memory, u, v, W_kv, W_q, W_p, W_out, mask.
// ---------------------------------------------------------------------------
extern "C" void kernel_launch(void* const* d_in, const int* in_sizes, int n_in,
                              void* d_out, int out_size)
{
    const float* input_ = (const float*)d_in[0];
    const float* pos    = (const float*)d_in[1];
    const float* memory = (const float*)d_in[2];
    const float* u      = (const float*)d_in[3];
    const float* v      = (const float*)d_in[4];
    const float* W_kv   = (const float*)d_in[5];
    const float* W_q    = (const float*)d_in[6];
    const float* W_p    = (const float*)d_in[7];
    const float* W_out  = (const float*)d_in[8];
    float* out = (float*)d_out;

    float *qvb, *qub, *kvb, *pb, *Pb, *aob;
    float *cin, *cmem, *cpos, *cWkv, *cWq, *cWp, *cWout;
    cudaGetSymbolAddress((void**)&qvb,  g_qv);
    cudaGetSymbolAddress((void**)&qub,  g_qu);
    cudaGetSymbolAddress((void**)&kvb,  g_kv);
    cudaGetSymbolAddress((void**)&pb,   g_p);
    cudaGetSymbolAddress((void**)&Pb,   g_P);
    cudaGetSymbolAddress((void**)&aob,  g_ao);
    cudaGetSymbolAddress((void**)&cin,  c_in);
    cudaGetSymbolAddress((void**)&cmem, c_mem);
    cudaGetSymbolAddress((void**)&cpos, c_pos);
    cudaGetSymbolAddress((void**)&cWkv, c_Wkv);
    cudaGetSymbolAddress((void**)&cWq,  c_Wq);
    cudaGetSymbolAddress((void**)&cWp,  c_Wp);
    cudaGetSymbolAddress((void**)&cWout, c_Wout);

    cudaFuncSetAttribute(gemm_tf32<0,0>, cudaFuncAttributeMaxDynamicSharedMemorySize, GEMM_SMEM);
    cudaFuncSetAttribute(gemm_tf32<0,1>, cudaFuncAttributeMaxDynamicSharedMemorySize, GEMM_SMEM);
    cudaFuncSetAttribute(gemm_tf32<0,2>, cudaFuncAttributeMaxDynamicSharedMemorySize, GEMM_SMEM);
    cudaFuncSetAttribute(gemm_tf32<1,1>, cudaFuncAttributeMaxDynamicSharedMemorySize, GEMM_SMEM);
    cudaFuncSetAttribute(pos_gemm_tf32,  cudaFuncAttributeMaxDynamicSharedMemorySize, POS_SMEM);
    cudaFuncSetAttribute(attn_fused,     cudaFuncAttributeMaxDynamicSharedMemorySize, ATT_SMEM);

    // ---- one-time tf32 conversion of external operands ----
    auto cvt = [&](const float* src, float* dst, size_t n) {
        int n4 = (int)(n / 4);
        cvt_tf32_k<<<(n4 + 255) / 256, 256>>>(src, dst, n4);
    };
    cvt(input_, cin,  (size_t)BSZ * CSQ * DIN);
    cvt(memory, cmem, (size_t)BSZ * PSQ * DIN);
    cvt(pos,    cpos, (size_t)TT * DIN);
    cvt(W_kv,   cWkv, (size_t)DIN * 2 * HD);
    cvt(W_q,    cWq,  (size_t)DIN * HD);
    cvt(W_p,    cWp,  (size_t)DIN * HD);
    cvt(W_out,  cWout,(size_t)HD * DIN);

    dim3 thr(128);

    // q-GEMM -> qv = tf32r(q+v), qu = tf32r(q+u)
    gemm_tf32<0,2><<<dim3(HD / 128, LQG / 128), thr, GEMM_SMEM>>>(
        cin, nullptr, cWq, qvb, qub, v, u, LQG, HD, DIN);
    // kv = concat(memory, input_) @ W_kv, rounded
    gemm_tf32<1,1><<<dim3(2 * HD / 128, (BSZ * TT) / 128), thr, GEMM_SMEM>>>(
        cmem, cin, cWkv, kvb, nullptr, nullptr, nullptr, BSZ * TT, 2 * HD, DIN);
    // p = pos_embs @ W_p, rounded
    gemm_tf32<0,1><<<dim3(HD / 128, TT / 128), thr, GEMM_SMEM>>>(
        cpos, nullptr, cWp, pb, nullptr, nullptr, nullptr, TT, HD, DIN);
    // P[h] = qv @ p^T per head
    pos_gemm_tf32<<<dim3(TT / 128, LQG / 128, NH), thr, POS_SMEM>>>(qvb, pb, Pb);
    // fused attention
    attn_fused<<<dim3(CSQ / 128, BSZ * NH), 256, ATT_SMEM>>>(qub, kvb, Pb, aob);
    // out = ao @ W_out (plain fp32 store)
    gemm_tf32<0,0><<<dim3(DIN / 128, LQG / 128), thr, GEMM_SMEM>>>(
        aob, nullptr, cWout, out, nullptr, nullptr, nullptr, LQG, DIN, HD);
}

// round 12
// speedup vs baseline: 1.5756x; 1.5756x over previous
#include <cuda_runtime.h>
#include <cuda_fp16.h>
#include <cstdint>

// Problem constants
#define BSZ   4
#define CSQ   1024
#define PSQ   1024
#define DIN   1024
#define NH    16
#define HDIM  64
#define TT    2048        // T = CS + PS
#define LQG   4096        // BSZ*CSQ global query rows
#define HD    1024        // NH*HDIM
#define SCALE 0.125f      // 1/sqrt(64)

// ---------------------------------------------------------------------------
// Scratch (device globals; no dynamic allocation allowed)
// ---------------------------------------------------------------------------
__device__ float g_q [(size_t)LQG * HD];                 //  16.8 MB  q_tfmd
__device__ float g_kv[(size_t)BSZ * TT * 2 * HD];        //  67 MB    [k | v]
__device__ float g_p [(size_t)TT * HD];                  //   8.4 MB  p_tfmd
__device__ float g_P [(size_t)NH * LQG * TT];            // 512 MB    pos scores
__device__ float g_ao[(size_t)LQG * HD];                 //  16.8 MB  attn out
// half-precision staging (one-time conversions)
__device__ __half h_in  [(size_t)BSZ * CSQ * DIN];       //  8.4 MB
__device__ __half h_mem [(size_t)BSZ * PSQ * DIN];       //  8.4 MB
__device__ __half h_pos [(size_t)TT * DIN];              //  4.2 MB
__device__ __half h_ao  [(size_t)LQG * HD];              //  8.4 MB
__device__ __half h_Wkv_t [(size_t)(2 * HD) * DIN];      //  4.2 MB  [n][k]
__device__ __half h_Wq_t  [(size_t)HD * DIN];            //  2.1 MB
__device__ __half h_Wp_t  [(size_t)HD * DIN];            //  2.1 MB
__device__ __half h_Wout_t[(size_t)DIN * HD];            //  2.1 MB

// ---------------------------------------------------------------------------
// Helpers
// ---------------------------------------------------------------------------
__device__ __forceinline__ float tf32r(float x) {
    float y;
    asm("cvt.rna.tf32.f32 %0, %1;" : "=f"(y) : "f"(x));
    return y;
}
__device__ __forceinline__ float4 tf32r4(float4 v) {
    return make_float4(tf32r(v.x), tf32r(v.y), tf32r(v.z), tf32r(v.w));
}

// tf32 m16n8k8 (used by pos_gemm / attn_fused, unchanged from R8)
__device__ __forceinline__ void mma8(float* d, const float* a, const float* b) {
    asm volatile(
        "mma.sync.aligned.m16n8k8.row.col.f32.tf32.tf32.f32 "
        "{%0,%1,%2,%3}, {%4,%5,%6,%7}, {%8,%9}, {%0,%1,%2,%3};"
        : "+f"(d[0]), "+f"(d[1]), "+f"(d[2]), "+f"(d[3])
        : "r"(__float_as_uint(a[0])), "r"(__float_as_uint(a[1])),
          "r"(__float_as_uint(a[2])), "r"(__float_as_uint(a[3])),
          "r"(__float_as_uint(b[0])), "r"(__float_as_uint(b[1])));
}

// fp16 m16n8k16, fp32 accumulate
__device__ __forceinline__ void mma16(float* d, const uint32_t* a, const uint32_t* b) {
    asm volatile(
        "mma.sync.aligned.m16n8k16.row.col.f32.f16.f16.f32 "
        "{%0,%1,%2,%3}, {%4,%5,%6,%7}, {%8,%9}, {%0,%1,%2,%3};"
        : "+f"(d[0]), "+f"(d[1]), "+f"(d[2]), "+f"(d[3])
        : "r"(a[0]), "r"(a[1]), "r"(a[2]), "r"(a[3]), "r"(b[0]), "r"(b[1]));
}

__device__ __forceinline__ uint32_t smem_u32(const void* p) {
    return (uint32_t)__cvta_generic_to_shared(p);
}
#define CPA16(dst, src) \
    asm volatile("cp.async.cg.shared.global [%0], [%1], 16;" :: "r"(dst), "l"(src))
#define CPA_COMMIT() asm volatile("cp.async.commit_group;")
#define CPA_WAIT(n)  asm volatile("cp.async.wait_group %0;" :: "n"(n))
#define CPA_WAIT_TAIL(rem) do {                         \
        if ((rem) >= 2)      CPA_WAIT(2);               \
        else if ((rem) == 1) CPA_WAIT(1);               \
        else                 CPA_WAIT(0);               \
    } while (0)

// ---------------------------------------------------------------------------
// Conversion kernels (one-time)
// ---------------------------------------------------------------------------
__global__ void __launch_bounds__(256) cvt_f2h(const float* __restrict__ in,
                                               __half* __restrict__ out, int n4)
{
    int i = blockIdx.x * 256 + threadIdx.x;
    if (i < n4) {
        float4 v = ((const float4*)in)[i];
        __half2* o = (__half2*)out + (size_t)i * 2;
        o[0] = __floats2half2_rn(v.x, v.y);
        o[1] = __floats2half2_rn(v.z, v.w);
    }
}

// W [K][N] fp32 -> Wt [N][K] half (tiled transpose)
__global__ void __launch_bounds__(256) transpose_f2h(const float* __restrict__ in,
                                                     __half* __restrict__ out,
                                                     int K, int N)
{
    __shared__ __half tile[32][33];
    int k0 = blockIdx.y * 32, n0 = blockIdx.x * 32;
    int tx = threadIdx.x & 31, ty = threadIdx.x >> 5;   // 32 x 8
#pragma unroll
    for (int i = 0; i < 32; i += 8)
        tile[ty + i][tx] = __float2half(in[(size_t)(k0 + ty + i) * N + n0 + tx]);
    __syncthreads();
#pragma unroll
    for (int i = 0; i < 32; i += 8)
        out[(size_t)(n0 + ty + i) * K + k0 + tx] = tile[tx][ty + i];
}

// ---------------------------------------------------------------------------
// fp16 NT GEMM: C(MxN fp32) = A(MxK half) @ Bt(NxK half)^T, tiles 128x128,
// K%32==0. MODE 0: A plain. MODE 1: A rows = concat(memory, input_) virtual.
// 128 threads = 4 warps 2(m)x2(n), warp tile 64x64 = 4x8 m16n8k16 tiles.
// 4-stage cp.async ring; both tiles staged [row][k] pitch 40 halves (80B,
// conflict-free). Inner k16: 32 LDS32 + 32 HMMA.
// Dynamic SMEM: 4 stages x (A 10240B + B 10240B) = 81920 B.
// ---------------------------------------------------------------------------
#define GEMMH_SMEM (4 * 20480)

template <int MODE>
__global__ void __launch_bounds__(128) gemm_fp16(
    const __half* __restrict__ A, const __half* __restrict__ A2,
    const __half* __restrict__ Bt, float* __restrict__ C,
    int M, int N, int K)
{
    extern __shared__ __half smh[];
    const uint32_t sbase = smem_u32(smh);
    const int tid  = threadIdx.x;
    const int lane = tid & 31;
    const int w    = tid >> 5;
    const int wm   = (w >> 1) * 64;
    const int wn   = (w & 1) * 64;
    const int bm   = blockIdx.y * 128;
    const int bn   = blockIdx.x * 128;
    const int r    = lane >> 2;
    const int kb   = lane & 3;

    const __half* arow;
    if (MODE == 0) {
        arow = A + (size_t)(bm + tid) * K;
    } else {
        int row = bm + tid;
        int b   = row / TT;
        int rr  = row - b * TT;
        arow = (rr < PSQ) ? A  + (size_t)(b * PSQ + rr)         * K
                          : A2 + (size_t)(b * CSQ + (rr - PSQ)) * K;
    }
    const __half* brow = Bt + (size_t)(bn + tid) * K;

    auto issue = [&](int s, int k0) {
        uint32_t ab = sbase + s * 20480 + tid * 80;
        uint32_t bb = ab + 10240;
#pragma unroll
        for (int j = 0; j < 4; j++) {
            CPA16(ab + j * 16, arow + k0 + j * 8);
            CPA16(bb + j * 16, brow + k0 + j * 8);
        }
        CPA_COMMIT();
    };

    const int T = K / 32;
    issue(0, 0); issue(1, 32); issue(2, 64);

    float acc[4][8][4] = {};

    for (int t = 0; t < T; t++) {
        CPA_WAIT_TAIL(T - 1 - t);
        __syncthreads();
        if (t + 3 < T) issue((t + 3) & 3, (t + 3) * 32);
        const char* sb = (const char*)smh + (t & 3) * 20480;
#pragma unroll
        for (int kk = 0; kk < 32; kk += 16) {
            const int koff = kk * 2 + kb * 4;
            uint32_t a[4][4], b[8][2];
#pragma unroll
            for (int mt = 0; mt < 4; mt++) {
                const char* ab = sb + (wm + mt * 16 + r) * 80 + koff;
                a[mt][0] = *(const uint32_t*)(ab);
                a[mt][1] = *(const uint32_t*)(ab + 640);       // +8 rows
                a[mt][2] = *(const uint32_t*)(ab + 16);        // +8 k
                a[mt][3] = *(const uint32_t*)(ab + 656);
            }
#pragma unroll
            for (int nt = 0; nt < 8; nt++) {
                const char* bb = sb + 10240 + (wn + nt * 8 + r) * 80 + koff;
                b[nt][0] = *(const uint32_t*)(bb);
                b[nt][1] = *(const uint32_t*)(bb + 16);
            }
#pragma unroll
            for (int mt = 0; mt < 4; mt++)
#pragma unroll
                for (int nt = 0; nt < 8; nt++)
                    mma16(acc[mt][nt], a[mt], b[nt]);
        }
    }

#pragma unroll
    for (int mt = 0; mt < 4; mt++) {
        int r0 = bm + wm + mt * 16 + r;
#pragma unroll
        for (int nt = 0; nt < 8; nt++) {
            int c0 = bn + wn + nt * 8 + kb * 2;
            *(float2*)&C[(size_t)r0 * N + c0]       = make_float2(acc[mt][nt][0], acc[mt][nt][1]);
            *(float2*)&C[(size_t)(r0 + 8) * N + c0] = make_float2(acc[mt][nt][2], acc[mt][nt][3]);
        }
    }
}

// ---------------------------------------------------------------------------
// P[h][L][jj] = sum_d (q[L,h,d]+v[h,d]) * p[jj,h,d]   (NT, K=64)
// (Verbatim from the 1762us R8 build.)
// ---------------------------------------------------------------------------
__global__ void __launch_bounds__(128) pos_gemm_tf32(
    const float* __restrict__ q, const float* __restrict__ p,
    const float* __restrict__ vb, float* __restrict__ P)
{
    __shared__ float As[16][136];
    __shared__ float Bs[16][136];
    const int tid  = threadIdx.x;
    const int lane = tid & 31;
    const int w    = tid >> 5;
    const int wm   = (w >> 1) * 64;
    const int wn   = (w & 1) * 64;
    const int h    = blockIdx.z;
    const int L0   = blockIdx.y * 128;
    const int j0   = blockIdx.x * 128;

    const float* arow = q  + (size_t)(L0 + tid) * HD + h * HDIM;
    const float* vrow = vb + h * HDIM;
    const float* brow = p  + (size_t)(j0 + tid) * HD + h * HDIM;

    float acc[4][8][4] = {};
    float4 sa[4], sv[4], sb[4];

#define NT_GL(k0) do {                                               \
        sa[0] = *(const float4*)(arow + (k0));                       \
        sa[1] = *(const float4*)(arow + (k0) + 4);                   \
        sa[2] = *(const float4*)(arow + (k0) + 8);                   \
        sa[3] = *(const float4*)(arow + (k0) + 12);                  \
        sv[0] = *(const float4*)(vrow + (k0));                       \
        sv[1] = *(const float4*)(vrow + (k0) + 4);                   \
        sv[2] = *(const float4*)(vrow + (k0) + 8);                   \
        sv[3] = *(const float4*)(vrow + (k0) + 12);                  \
        sb[0] = *(const float4*)(brow + (k0));                       \
        sb[1] = *(const float4*)(brow + (k0) + 4);                   \
        sb[2] = *(const float4*)(brow + (k0) + 8);                   \
        sb[3] = *(const float4*)(brow + (k0) + 12);                  \
    } while (0)
#define NT_STORE() do {                                                          \
        _Pragma("unroll")                                                        \
        for (int i = 0; i < 4; i++) {                                            \
            As[i*4+0][tid] = tf32r(((const float*)&sa[i])[0] + ((const float*)&sv[i])[0]); \
            As[i*4+1][tid] = tf32r(((const float*)&sa[i])[1] + ((const float*)&sv[i])[1]); \
            As[i*4+2][tid] = tf32r(((const float*)&sa[i])[2] + ((const float*)&sv[i])[2]); \
            As[i*4+3][tid] = tf32r(((const float*)&sa[i])[3] + ((const float*)&sv[i])[3]); \
            Bs[i*4+0][tid] = tf32r(((const float*)&sb[i])[0]);                   \
            Bs[i*4+1][tid] = tf32r(((const float*)&sb[i])[1]);                   \
            Bs[i*4+2][tid] = tf32r(((const float*)&sb[i])[2]);                   \
            Bs[i*4+3][tid] = tf32r(((const float*)&sb[i])[3]);                   \
        }                                                                        \
    } while (0)

    NT_GL(0); NT_STORE(); __syncthreads();
#pragma unroll
    for (int k0 = 0; k0 < HDIM; k0 += 16) {
        const bool more = (k0 + 16 < HDIM);
        if (more) NT_GL(k0 + 16);
#pragma unroll
        for (int kk = 0; kk < 16; kk += 8) {
            const int kr = kk + (lane & 3);
            const int ms = lane >> 2;
            float a[4][4], b[8][2];
#pragma unroll
            for (int mt = 0; mt < 4; mt++) {
                a[mt][0] = As[kr][wm + mt * 16 + ms];
                a[mt][1] = As[kr][wm + mt * 16 + ms + 8];
                a[mt][2] = As[kr + 4][wm + mt * 16 + ms];
                a[mt][3] = As[kr + 4][wm + mt * 16 + ms + 8];
            }
#pragma unroll
            for (int nt = 0; nt < 8; nt++) {
                b[nt][0] = Bs[kr][wn + nt * 8 + ms];
                b[nt][1] = Bs[kr + 4][wn + nt * 8 + ms];
            }
#pragma unroll
            for (int mt = 0; mt < 4; mt++)
#pragma unroll
                for (int nt = 0; nt < 8; nt++)
                    mma8(acc[mt][nt], a[mt], b[nt]);
        }
        if (more) { __syncthreads(); NT_STORE(); __syncthreads(); }
    }
#undef NT_GL
#undef NT_STORE

#pragma unroll
    for (int mt = 0; mt < 4; mt++) {
        int r0 = L0 + wm + mt * 16 + (lane >> 2);
#pragma unroll
        for (int nt = 0; nt < 8; nt++) {
            int c0 = j0 + wn + nt * 8 + (lane & 3) * 2;
            float* o = P + ((size_t)h * LQG + r0) * TT + c0;
            *(float2*)o            = make_float2(acc[mt][nt][0], acc[mt][nt][1]);
            *(float2*)(o + 8 * TT) = make_float2(acc[mt][nt][2], acc[mt][nt][3]);
        }
    }
}

// ---------------------------------------------------------------------------
// rel_shift gather: pos(b,i,j) with L = b*CS+i
// ---------------------------------------------------------------------------
__device__ __forceinline__ float pos_val(const float* __restrict__ Pm,
                                         int h, int L, int jj)
{
    int s  = jj + LQG - L;
    int n  = (s > TT) + (s > 2 * TT + 1);
    int jp = s - n * (TT + 1);
    int Lp = L + n;
    float pos = 0.f;
    if (jp > 0 && Lp < LQG)
        pos = Pm[((size_t)h * LQG + Lp) * TT + (jp - 1)];
    return pos;
}

// ---------------------------------------------------------------------------
// Fused attention (verbatim from the 1762us R8 build).
// ---------------------------------------------------------------------------
#define ATT_SMEM ((64 * 136 + 64 * 72 + 64 * 72) * 4)

__global__ void __launch_bounds__(256) attn_fused(
    const float* __restrict__ q, const float* __restrict__ kv,
    const float* __restrict__ ub, const float* __restrict__ Pm,
    float* __restrict__ ao)
{
    extern __shared__ float dyn[];
    float (*Sp)[136] = (float(*)[136])dyn;
    float (*Bk)[72]  = (float(*)[72])(dyn + 64 * 136);
    float (*Bv)[72]  = (float(*)[72])(dyn + 64 * 136 + 64 * 72);

    const int tid  = threadIdx.x;
    const int lane = tid & 31;
    const int w    = tid >> 5;
    const int wm   = w * 16;
    const int bh   = blockIdx.y;
    const int b    = bh >> 4;
    const int h    = bh & 15;
    const int i0   = blockIdx.x * 128;
    const int r    = lane >> 2;
    const int kb   = lane & 3;

    {
        int row = tid >> 1;
        int kq  = (tid & 1) * 32;
        const float* qr = q  + (size_t)(b * CSQ + i0 + row) * HD + h * HDIM + kq;
        const float* ur = ub + h * HDIM + kq;
#pragma unroll
        for (int i = 0; i < 8; i++) {
            float4 a  = *(const float4*)(qr + i * 4);
            float4 uu = *(const float4*)(ur + i * 4);
            Sp[kq + i * 4 + 0][row] = tf32r(a.x + uu.x);
            Sp[kq + i * 4 + 1][row] = tf32r(a.y + uu.y);
            Sp[kq + i * 4 + 2][row] = tf32r(a.z + uu.z);
            Sp[kq + i * 4 + 3][row] = tf32r(a.w + uu.w);
        }
    }
    __syncthreads();
    float aq[8][4];
#pragma unroll
    for (int ks = 0; ks < 8; ks++) {
        aq[ks][0] = Sp[ks * 8 + kb][wm + r];
        aq[ks][1] = Sp[ks * 8 + kb][wm + r + 8];
        aq[ks][2] = Sp[ks * 8 + kb + 4][wm + r];
        aq[ks][3] = Sp[ks * 8 + kb + 4][wm + r + 8];
    }
    __syncthreads();

    float m0 = -3.0e38f, m1 = -3.0e38f, l0 = 0.f, l1 = 0.f;
    float acc_o[8][4] = {};

    const int row0 = i0 + wm + r;
    const int Lr   = b * CSQ + row0;
    const int Kef  = min(TT, i0 + 128 + PSQ);

    for (int j0 = 0; j0 < Kef; j0 += 64) {
        {
            int j  = tid & 63;
            int dq = (tid >> 6) * 16;
            const float* kr_ = kv + ((size_t)(b * TT + j0 + j)) * (2 * HD) + h * HDIM + dq;
#pragma unroll
            for (int i = 0; i < 4; i++) {
                float4 kx = *(const float4*)(kr_ + i * 4);
                Bk[dq + i * 4 + 0][j] = tf32r(kx.x);
                Bk[dq + i * 4 + 1][j] = tf32r(kx.y);
                Bk[dq + i * 4 + 2][j] = tf32r(kx.z);
                Bk[dq + i * 4 + 3][j] = tf32r(kx.w);
            }
            const float* vr_ = kr_ + HD;
#pragma unroll
            for (int i = 0; i < 4; i++) {
                float4 vx = *(const float4*)(vr_ + i * 4);
                *(float4*)&Bv[j][dq + i * 4] = tf32r4(vx);
            }
        }
        __syncthreads();

        float s[8][4] = {};
#pragma unroll
        for (int ks = 0; ks < 8; ks++) {
            float bq[8][2];
#pragma unroll
            for (int nt = 0; nt < 8; nt++) {
                bq[nt][0] = Bk[ks * 8 + kb][nt * 8 + r];
                bq[nt][1] = Bk[ks * 8 + kb + 4][nt * 8 + r];
            }
#pragma unroll
            for (int nt = 0; nt < 8; nt++)
                mma8(s[nt], aq[ks], bq[nt]);
        }

#pragma unroll
        for (int nt = 0; nt < 8; nt++) {
            int jjb = j0 + nt * 8 + 2 * kb;
#pragma unroll
            for (int cc = 0; cc < 2; cc++) {
                int jj = jjb + cc;
                s[nt][cc]     = (jj > row0 + PSQ)     ? -1e30f
                              : (s[nt][cc]     + pos_val(Pm, h, Lr, jj))     * SCALE;
                s[nt][2 + cc] = (jj > row0 + 8 + PSQ) ? -1e30f
                              : (s[nt][2 + cc] + pos_val(Pm, h, Lr + 8, jj)) * SCALE;
            }
        }

        float tm0 = -3.0e38f, tm1 = -3.0e38f;
#pragma unroll
        for (int nt = 0; nt < 8; nt++) {
            tm0 = fmaxf(tm0, fmaxf(s[nt][0], s[nt][1]));
            tm1 = fmaxf(tm1, fmaxf(s[nt][2], s[nt][3]));
        }
        tm0 = fmaxf(tm0, __shfl_xor_sync(0xffffffffu, tm0, 1));
        tm0 = fmaxf(tm0, __shfl_xor_sync(0xffffffffu, tm0, 2));
        tm1 = fmaxf(tm1, __shfl_xor_sync(0xffffffffu, tm1, 1));
        tm1 = fmaxf(tm1, __shfl_xor_sync(0xffffffffu, tm1, 2));
        float mn0 = fmaxf(m0, tm0), mn1 = fmaxf(m1, tm1);
        float f0 = __expf(m0 - mn0), f1 = __expf(m1 - mn1);

        float ps0 = 0.f, ps1 = 0.f;
#pragma unroll
        for (int nt = 0; nt < 8; nt++) {
            s[nt][0] = __expf(s[nt][0] - mn0);
            s[nt][1] = __expf(s[nt][1] - mn0);
            s[nt][2] = __expf(s[nt][2] - mn1);
            s[nt][3] = __expf(s[nt][3] - mn1);
            ps0 += s[nt][0] + s[nt][1];
            ps1 += s[nt][2] + s[nt][3];
        }
        ps0 += __shfl_xor_sync(0xffffffffu, ps0, 1);
        ps0 += __shfl_xor_sync(0xffffffffu, ps0, 2);
        ps1 += __shfl_xor_sync(0xffffffffu, ps1, 1);
        ps1 += __shfl_xor_sync(0xffffffffu, ps1, 2);
        l0 = l0 * f0 + ps0;
        l1 = l1 * f1 + ps1;
        m0 = mn0; m1 = mn1;

#pragma unroll
        for (int nt = 0; nt < 8; nt++) {
            acc_o[nt][0] *= f0; acc_o[nt][1] *= f0;
            acc_o[nt][2] *= f1; acc_o[nt][3] *= f1;
        }

#pragma unroll
        for (int nt = 0; nt < 8; nt++) {
            int jl = nt * 8 + 2 * kb;
            Sp[jl    ][wm + r]     = tf32r(s[nt][0]);
            Sp[jl + 1][wm + r]     = tf32r(s[nt][1]);
            Sp[jl    ][wm + r + 8] = tf32r(s[nt][2]);
            Sp[jl + 1][wm + r + 8] = tf32r(s[nt][3]);
        }
        __syncwarp();

#pragma unroll
        for (int kj = 0; kj < 8; kj++) {
            float a[4];
            a[0] = Sp[kj * 8 + kb][wm + r];
            a[1] = Sp[kj * 8 + kb][wm + r + 8];
            a[2] = Sp[kj * 8 + kb + 4][wm + r];
            a[3] = Sp[kj * 8 + kb + 4][wm + r + 8];
            float bq[8][2];
#pragma unroll
            for (int nt = 0; nt < 8; nt++) {
                bq[nt][0] = Bv[kj * 8 + kb][nt * 8 + r];
                bq[nt][1] = Bv[kj * 8 + kb + 4][nt * 8 + r];
            }
#pragma unroll
            for (int nt = 0; nt < 8; nt++)
                mma8(acc_o[nt], a, bq[nt]);
        }
        __syncthreads();
    }

    float inv0 = 1.0f / l0, inv1 = 1.0f / l1;
#pragma unroll
    for (int nt = 0; nt < 8; nt++) {
        int c0 = nt * 8 + 2 * kb;
        float* o0 = ao + (size_t)(b * CSQ + row0) * HD + h * HDIM + c0;
        *(float2*)o0            = make_float2(acc_o[nt][0] * inv0, acc_o[nt][1] * inv0);
        *(float2*)(o0 + 8 * HD) = make_float2(acc_o[nt][2] * inv1, acc_o[nt][3] * inv1);
    }
}

// ---------------------------------------------------------------------------
// Launch. Inputs: input_, pos_embs, memory, u, v, W_kv, W_q, W_p, W_out, mask.
// ---------------------------------------------------------------------------
extern "C" void kernel_launch(void* const* d_in, const int* in_sizes, int n_in,
                              void* d_out, int out_size)
{
    const float* input_ = (const float*)d_in[0];
    const float* pos    = (const float*)d_in[1];
    const float* memory = (const float*)d_in[2];
    const float* u      = (const float*)d_in[3];
    const float* v      = (const float*)d_in[4];
    const float* W_kv   = (const float*)d_in[5];
    const float* W_q    = (const float*)d_in[6];
    const float* W_p    = (const float*)d_in[7];
    const float* W_out  = (const float*)d_in[8];
    float* out = (float*)d_out;

    float *qb, *kvb, *pb, *Pb, *aob;
    __half *hin, *hmem, *hpos, *hao, *hWkv, *hWq, *hWp, *hWout;
    cudaGetSymbolAddress((void**)&qb,   g_q);
    cudaGetSymbolAddress((void**)&kvb,  g_kv);
    cudaGetSymbolAddress((void**)&pb,   g_p);
    cudaGetSymbolAddress((void**)&Pb,   g_P);
    cudaGetSymbolAddress((void**)&aob,  g_ao);
    cudaGetSymbolAddress((void**)&hin,  h_in);
    cudaGetSymbolAddress((void**)&hmem, h_mem);
    cudaGetSymbolAddress((void**)&hpos, h_pos);
    cudaGetSymbolAddress((void**)&hao,  h_ao);
    cudaGetSymbolAddress((void**)&hWkv, h_Wkv_t);
    cudaGetSymbolAddress((void**)&hWq,  h_Wq_t);
    cudaGetSymbolAddress((void**)&hWp,  h_Wp_t);
    cudaGetSymbolAddress((void**)&hWout, h_Wout_t);

    cudaFuncSetAttribute(gemm_fp16<0>, cudaFuncAttributeMaxDynamicSharedMemorySize, GEMMH_SMEM);
    cudaFuncSetAttribute(gemm_fp16<1>, cudaFuncAttributeMaxDynamicSharedMemorySize, GEMMH_SMEM);
    cudaFuncSetAttribute(attn_fused,   cudaFuncAttributeMaxDynamicSharedMemorySize, ATT_SMEM);

    // ---- one-time conversions ----
    auto cvt = [&](const float* src, __half* dst, size_t n) {
        int n4 = (int)(n / 4);
        cvt_f2h<<<(n4 + 255) / 256, 256>>>(src, dst, n4);
    };
    cvt(input_, hin,  (size_t)BSZ * CSQ * DIN);
    cvt(memory, hmem, (size_t)BSZ * PSQ * DIN);
    cvt(pos,    hpos, (size_t)TT * DIN);
    transpose_f2h<<<dim3(HD / 32,     DIN / 32), 256>>>(W_q,   hWq,   DIN, HD);
    transpose_f2h<<<dim3(2 * HD / 32, DIN / 32), 256>>>(W_kv,  hWkv,  DIN, 2 * HD);
    transpose_f2h<<<dim3(HD / 32,     DIN / 32), 256>>>(W_p,   hWp,   DIN, HD);
    transpose_f2h<<<dim3(DIN / 32,    HD / 32),  256>>>(W_out, hWout, HD,  DIN);

    dim3 thr(128);

    // q = input_ @ W_q                      (4096 x 1024 x 1024)  [fp16 HMMA]
    gemm_fp16<0><<<dim3(HD / 128, LQG / 128), thr, GEMMH_SMEM>>>(
        hin, nullptr, hWq, qb, LQG, HD, DIN);
    // kv = concat(memory, input_) @ W_kv    (8192 x 2048 x 1024)  [fp16 HMMA]
    gemm_fp16<1><<<dim3(2 * HD / 128, (BSZ * TT) / 128), thr, GEMMH_SMEM>>>(
        hmem, hin, hWkv, kvb, BSZ * TT, 2 * HD, DIN);
    // p = pos_embs @ W_p                    (2048 x 1024 x 1024)  [fp16 HMMA]
    gemm_fp16<0><<<dim3(HD / 128, TT / 128), thr, GEMMH_SMEM>>>(
        hpos, nullptr, hWp, pb, TT, HD, DIN);
    // P[h] = (q + v) @ p^T per head         (16 x 4096 x 2048 x 64)
    pos_gemm_tf32<<<dim3(TT / 128, LQG / 128, NH), thr>>>(qb, pb, v, Pb);
    // fused: scores + rel-shift + mask + online softmax + attn@V
    attn_fused<<<dim3(CSQ / 128, BSZ * NH), 256, ATT_SMEM>>>(qb, kvb, u, Pb, aob);
    // ao -> half, then out = ao @ W_out     (4096 x 1024 x 1024)  [fp16 HMMA]
    cvt(aob, hao, (size_t)LQG * HD);
    gemm_fp16<0><<<dim3(DIN / 128, LQG / 128), thr, GEMMH_SMEM>>>(
        hao, nullptr, hWout, out, LQG, DIN, HD);
}

// round 13
// speedup vs baseline: 1.8341x; 1.1641x over previous
#include <cuda_runtime.h>
#include <cuda_fp16.h>
#include <cstdint>

// Problem constants
#define BSZ   4
#define CSQ   1024
#define PSQ   1024
#define DIN   1024
#define NH    16
#define HDIM  64
#define TT    2048        // T = CS + PS
#define LQG   4096        // BSZ*CSQ global query rows
#define HD    1024        // NH*HDIM
#define SCALE 0.125f      // 1/sqrt(64)

// ---------------------------------------------------------------------------
// Scratch (device globals; no dynamic allocation allowed)
// ---------------------------------------------------------------------------
__device__ float  g_P  [(size_t)NH * LQG * TT];          // 512 MB  pos scores (fp32)
__device__ __half h_qv [(size_t)LQG * HD];               //  8.4 MB half(q+v)
__device__ __half h_qu [(size_t)LQG * HD];               //  8.4 MB half(q+u)
__device__ __half h_kvh[(size_t)BSZ * TT * 2 * HD];      // 33.5 MB [k|v] half
__device__ __half h_ph [(size_t)TT * HD];                //  4.2 MB p half
__device__ __half h_aoh[(size_t)LQG * HD];               //  8.4 MB attn out half
// half inputs / transposed weights (one-time conversions)
__device__ __half h_in  [(size_t)BSZ * CSQ * DIN];
__device__ __half h_mem [(size_t)BSZ * PSQ * DIN];
__device__ __half h_pos [(size_t)TT * DIN];
__device__ __half h_Wkv_t [(size_t)(2 * HD) * DIN];      // [n][k]
__device__ __half h_Wq_t  [(size_t)HD * DIN];
__device__ __half h_Wp_t  [(size_t)HD * DIN];
__device__ __half h_Wout_t[(size_t)DIN * HD];

// ---------------------------------------------------------------------------
// Helpers
// ---------------------------------------------------------------------------
__device__ __forceinline__ void mma16(float* d, const uint32_t* a, const uint32_t* b) {
    asm volatile(
        "mma.sync.aligned.m16n8k16.row.col.f32.f16.f16.f32 "
        "{%0,%1,%2,%3}, {%4,%5,%6,%7}, {%8,%9}, {%0,%1,%2,%3};"
        : "+f"(d[0]), "+f"(d[1]), "+f"(d[2]), "+f"(d[3])
        : "r"(a[0]), "r"(a[1]), "r"(a[2]), "r"(a[3]), "r"(b[0]), "r"(b[1]));
}

__device__ __forceinline__ uint32_t smem_u32(const void* p) {
    return (uint32_t)__cvta_generic_to_shared(p);
}
#define CPA16(dst, src) \
    asm volatile("cp.async.cg.shared.global [%0], [%1], 16;" :: "r"(dst), "l"(src))
#define CPA_COMMIT() asm volatile("cp.async.commit_group;")
#define CPA_WAIT(n)  asm volatile("cp.async.wait_group %0;" :: "n"(n))
#define CPA_WAIT_TAIL(rem) do {                         \
        if ((rem) >= 2)      CPA_WAIT(2);               \
        else if ((rem) == 1) CPA_WAIT(1);               \
        else                 CPA_WAIT(0);               \
    } while (0)

// ---------------------------------------------------------------------------
// Conversion kernels (one-time)
// ---------------------------------------------------------------------------
__global__ void __launch_bounds__(256) cvt_f2h(const float* __restrict__ in,
                                               __half* __restrict__ out, int n4)
{
    int i = blockIdx.x * 256 + threadIdx.x;
    if (i < n4) {
        float4 v = ((const float4*)in)[i];
        __half2* o = (__half2*)out + (size_t)i * 2;
        o[0] = __floats2half2_rn(v.x, v.y);
        o[1] = __floats2half2_rn(v.z, v.w);
    }
}

// W [K][N] fp32 -> Wt [N][K] half (tiled transpose)
__global__ void __launch_bounds__(256) transpose_f2h(const float* __restrict__ in,
                                                     __half* __restrict__ out,
                                                     int K, int N)
{
    __shared__ __half tile[32][33];
    int k0 = blockIdx.y * 32, n0 = blockIdx.x * 32;
    int tx = threadIdx.x & 31, ty = threadIdx.x >> 5;   // 32 x 8
#pragma unroll
    for (int i = 0; i < 32; i += 8)
        tile[ty + i][tx] = __float2half(in[(size_t)(k0 + ty + i) * N + n0 + tx]);
    __syncthreads();
#pragma unroll
    for (int i = 0; i < 32; i += 8)
        out[(size_t)(n0 + ty + i) * K + k0 + tx] = tile[tx][ty + i];
}

// ---------------------------------------------------------------------------
// fp16 NT GEMM: A(MxK half) @ Bt(NxK half)^T, tiles 128x128, K%32==0.
// MODE 0: A plain. MODE 1: A rows = concat(memory, input_) virtual.
// EPI 0: fp32 C. EPI 1: half Ch. EPI 2: dual half: Ch=half(acc+Vb), C2h=half(acc+Ub).
// 128 threads = 4 warps 2(m)x2(n), warp 64x64; 4-stage cp.async ring,
// both tiles [row][k] pitch 40 halves (80B, conflict-free).
// ---------------------------------------------------------------------------
#define GEMMH_SMEM (4 * 20480)

template <int MODE, int EPI>
__global__ void __launch_bounds__(128) gemm_fp16(
    const __half* __restrict__ A, const __half* __restrict__ A2,
    const __half* __restrict__ Bt,
    float* __restrict__ C, __half* __restrict__ Ch, __half* __restrict__ C2h,
    const float* __restrict__ Vb, const float* __restrict__ Ub,
    int M, int N, int K)
{
    extern __shared__ __half smh[];
    const uint32_t sbase = smem_u32(smh);
    const int tid  = threadIdx.x;
    const int lane = tid & 31;
    const int w    = tid >> 5;
    const int wm   = (w >> 1) * 64;
    const int wn   = (w & 1) * 64;
    const int bm   = blockIdx.y * 128;
    const int bn   = blockIdx.x * 128;
    const int r    = lane >> 2;
    const int kb   = lane & 3;

    const __half* arow;
    if (MODE == 0) {
        arow = A + (size_t)(bm + tid) * K;
    } else {
        int row = bm + tid;
        int b   = row / TT;
        int rr  = row - b * TT;
        arow = (rr < PSQ) ? A  + (size_t)(b * PSQ + rr)         * K
                          : A2 + (size_t)(b * CSQ + (rr - PSQ)) * K;
    }
    const __half* brow = Bt + (size_t)(bn + tid) * K;

    auto issue = [&](int s, int k0) {
        uint32_t ab = sbase + s * 20480 + tid * 80;
        uint32_t bb = ab + 10240;
#pragma unroll
        for (int j = 0; j < 4; j++) {
            CPA16(ab + j * 16, arow + k0 + j * 8);
            CPA16(bb + j * 16, brow + k0 + j * 8);
        }
        CPA_COMMIT();
    };

    const int T = K / 32;
    issue(0, 0); issue(1, 32); issue(2, 64);

    float acc[4][8][4] = {};

    for (int t = 0; t < T; t++) {
        CPA_WAIT_TAIL(T - 1 - t);
        __syncthreads();
        if (t + 3 < T) issue((t + 3) & 3, (t + 3) * 32);
        const char* sb = (const char*)smh + (t & 3) * 20480;
#pragma unroll
        for (int kk = 0; kk < 32; kk += 16) {
            const int koff = kk * 2 + kb * 4;
            uint32_t a[4][4], b[8][2];
#pragma unroll
            for (int mt = 0; mt < 4; mt++) {
                const char* ab = sb + (wm + mt * 16 + r) * 80 + koff;
                a[mt][0] = *(const uint32_t*)(ab);
                a[mt][1] = *(const uint32_t*)(ab + 640);
                a[mt][2] = *(const uint32_t*)(ab + 16);
                a[mt][3] = *(const uint32_t*)(ab + 656);
            }
#pragma unroll
            for (int nt = 0; nt < 8; nt++) {
                const char* bb = sb + 10240 + (wn + nt * 8 + r) * 80 + koff;
                b[nt][0] = *(const uint32_t*)(bb);
                b[nt][1] = *(const uint32_t*)(bb + 16);
            }
#pragma unroll
            for (int mt = 0; mt < 4; mt++)
#pragma unroll
                for (int nt = 0; nt < 8; nt++)
                    mma16(acc[mt][nt], a[mt], b[nt]);
        }
    }

#pragma unroll
    for (int mt = 0; mt < 4; mt++) {
        int r0 = bm + wm + mt * 16 + r;
#pragma unroll
        for (int nt = 0; nt < 8; nt++) {
            int c0 = bn + wn + nt * 8 + kb * 2;
            if (EPI == 0) {
                *(float2*)&C[(size_t)r0 * N + c0]       = make_float2(acc[mt][nt][0], acc[mt][nt][1]);
                *(float2*)&C[(size_t)(r0 + 8) * N + c0] = make_float2(acc[mt][nt][2], acc[mt][nt][3]);
            } else if (EPI == 1) {
                *(__half2*)&Ch[(size_t)r0 * N + c0]       = __floats2half2_rn(acc[mt][nt][0], acc[mt][nt][1]);
                *(__half2*)&Ch[(size_t)(r0 + 8) * N + c0] = __floats2half2_rn(acc[mt][nt][2], acc[mt][nt][3]);
            } else {
                float v0 = Vb[c0], v1 = Vb[c0 + 1];
                float u0 = Ub[c0], u1 = Ub[c0 + 1];
                *(__half2*)&Ch[(size_t)r0 * N + c0]        = __floats2half2_rn(acc[mt][nt][0] + v0, acc[mt][nt][1] + v1);
                *(__half2*)&Ch[(size_t)(r0 + 8) * N + c0]  = __floats2half2_rn(acc[mt][nt][2] + v0, acc[mt][nt][3] + v1);
                *(__half2*)&C2h[(size_t)r0 * N + c0]       = __floats2half2_rn(acc[mt][nt][0] + u0, acc[mt][nt][1] + u1);
                *(__half2*)&C2h[(size_t)(r0 + 8) * N + c0] = __floats2half2_rn(acc[mt][nt][2] + u0, acc[mt][nt][3] + u1);
            }
        }
    }
}

// ---------------------------------------------------------------------------
// P[h][L][jj] = sum_d qv[L,h,d] * p[jj,h,d]   (NT, K=64, fp16 HMMA)
// Single SMEM stage (whole K): both tiles [row][k=64] pitch 72 halves
// (144B; conflict-free: addr mod 128 = 16r + 4kb, distinct per lane).
// ---------------------------------------------------------------------------
__global__ void __launch_bounds__(128) pos_gemm_fp16(
    const __half* __restrict__ qv, const __half* __restrict__ p,
    float* __restrict__ P)
{
    __shared__ __half As[128][72];
    __shared__ __half Bs[128][72];
    const int tid  = threadIdx.x;
    const int lane = tid & 31;
    const int w    = tid >> 5;
    const int wm   = (w >> 1) * 64;
    const int wn   = (w & 1) * 64;
    const int h    = blockIdx.z;
    const int L0   = blockIdx.y * 128;
    const int j0   = blockIdx.x * 128;
    const int r    = lane >> 2;
    const int kb   = lane & 3;

    {
        const __half* ar = qv + (size_t)(L0 + tid) * HD + h * HDIM;
        const __half* br = p  + (size_t)(j0 + tid) * HD + h * HDIM;
        uint32_t ad = smem_u32(&As[tid][0]);
        uint32_t bd = smem_u32(&Bs[tid][0]);
#pragma unroll
        for (int j = 0; j < 8; j++) {
            CPA16(ad + j * 16, ar + j * 8);
            CPA16(bd + j * 16, br + j * 8);
        }
        CPA_COMMIT();
    }
    CPA_WAIT(0);
    __syncthreads();

    float acc[4][8][4] = {};
#pragma unroll
    for (int ks = 0; ks < 4; ks++) {
        const int koff = ks * 16 + kb * 2;
        uint32_t a[4][4], b[8][2];
#pragma unroll
        for (int mt = 0; mt < 4; mt++) {
            a[mt][0] = *(const uint32_t*)&As[wm + mt * 16 + r][koff];
            a[mt][1] = *(const uint32_t*)&As[wm + mt * 16 + r + 8][koff];
            a[mt][2] = *(const uint32_t*)&As[wm + mt * 16 + r][koff + 8];
            a[mt][3] = *(const uint32_t*)&As[wm + mt * 16 + r + 8][koff + 8];
        }
#pragma unroll
        for (int nt = 0; nt < 8; nt++) {
            b[nt][0] = *(const uint32_t*)&Bs[wn + nt * 8 + r][koff];
            b[nt][1] = *(const uint32_t*)&Bs[wn + nt * 8 + r][koff + 8];
        }
#pragma unroll
        for (int mt = 0; mt < 4; mt++)
#pragma unroll
            for (int nt = 0; nt < 8; nt++)
                mma16(acc[mt][nt], a[mt], b[nt]);
    }

#pragma unroll
    for (int mt = 0; mt < 4; mt++) {
        int r0 = L0 + wm + mt * 16 + r;
#pragma unroll
        for (int nt = 0; nt < 8; nt++) {
            int c0 = j0 + wn + nt * 8 + kb * 2;
            float* o = P + ((size_t)h * LQG + r0) * TT + c0;
            *(float2*)o            = make_float2(acc[mt][nt][0], acc[mt][nt][1]);
            *(float2*)(o + 8 * TT) = make_float2(acc[mt][nt][2], acc[mt][nt][3]);
        }
    }
}

// ---------------------------------------------------------------------------
// rel_shift gather: pos(b,i,j) with L = b*CS+i
// ---------------------------------------------------------------------------
__device__ __forceinline__ float pos_val(const float* __restrict__ Pm,
                                         int h, int L, int jj)
{
    int s  = jj + LQG - L;
    int n  = (s > TT) + (s > 2 * TT + 1);
    int jp = s - n * (TT + 1);
    int Lp = L + n;
    float pos = 0.f;
    if (jp > 0 && Lp < LQG)
        pos = Pm[((size_t)h * LQG + Lp) * TT + (jp - 1)];
    return pos;
}

// ---------------------------------------------------------------------------
// Fused attention, fp16 MMA path.
// One CTA = 128 query rows of one (b,h); 8 warps, warp w owns rows
// [i0+16w, i0+16w+16). qu fragments preloaded from half; K tile copied
// directly (kv half is k-major = B-fragment layout); V staged transposed
// [d][j]; probs stored as half2 pairs. Score + PV both m16n8k16.
// SMEM (half): Sq/Sp 128*72 | Bk 64*72 | Bv 64*72  = 36864 B.
// ---------------------------------------------------------------------------
#define ATT_SMEM ((128 * 72 + 64 * 72 + 64 * 72) * 2)

__global__ void __launch_bounds__(256) attn_fused_fp16(
    const __half* __restrict__ qu, const __half* __restrict__ kv,
    const float* __restrict__ Pm, __half* __restrict__ ao)
{
    extern __shared__ __half dynh[];
    __half (*Sq)[72] = (__half(*)[72])dynh;                 // q staging, then probs
    __half (*Bk)[72] = (__half(*)[72])(dynh + 128 * 72);
    __half (*Bv)[72] = (__half(*)[72])(dynh + 128 * 72 + 64 * 72);

    const int tid  = threadIdx.x;
    const int lane = tid & 31;
    const int w    = tid >> 5;
    const int wm   = w * 16;
    const int bh   = blockIdx.y;
    const int b    = bh >> 4;
    const int h    = bh & 15;
    const int i0   = blockIdx.x * 128;
    const int r    = lane >> 2;
    const int kb   = lane & 3;

    // ---- stage qu rows, preload persistent A-fragments ----
    {
        int row = tid >> 1;
        int kq  = (tid & 1) * 32;
        const __half* qr = qu + (size_t)(b * CSQ + i0 + row) * HD + h * HDIM + kq;
#pragma unroll
        for (int i = 0; i < 4; i++)
            *(uint4*)&Sq[row][kq + i * 8] = *(const uint4*)(qr + i * 8);
    }
    __syncthreads();
    uint32_t aq[4][4];
#pragma unroll
    for (int ks = 0; ks < 4; ks++) {
        const int koff = ks * 16 + kb * 2;
        aq[ks][0] = *(const uint32_t*)&Sq[wm + r][koff];
        aq[ks][1] = *(const uint32_t*)&Sq[wm + r + 8][koff];
        aq[ks][2] = *(const uint32_t*)&Sq[wm + r][koff + 8];
        aq[ks][3] = *(const uint32_t*)&Sq[wm + r + 8][koff + 8];
    }
    __syncthreads();   // Sq region now free for probs

    float m0 = -3.0e38f, m1 = -3.0e38f, l0 = 0.f, l1 = 0.f;
    float acc_o[8][4] = {};

    const int row0 = i0 + wm + r;
    const int Lr   = b * CSQ + row0;
    const int Kef  = min(TT, i0 + 128 + PSQ);

    for (int j0 = 0; j0 < Kef; j0 += 64) {
        // ---- stage K (direct) and V (transposed) ----
        {
            int j  = tid & 63;
            int q4 = tid >> 6;   // 0..3, 16 halves each
            const __half* kr = kv + (size_t)(b * TT + j0 + j) * (2 * HD) + h * HDIM + q4 * 16;
            *(uint4*)&Bk[j][q4 * 16]     = *(const uint4*)(kr);
            *(uint4*)&Bk[j][q4 * 16 + 8] = *(const uint4*)(kr + 8);
            const __half* vr = kr + HD;
            uint4 v0 = *(const uint4*)(vr);
            uint4 v1 = *(const uint4*)(vr + 8);
            const __half* hv0 = (const __half*)&v0;
            const __half* hv1 = (const __half*)&v1;
#pragma unroll
            for (int i = 0; i < 8; i++) {
                Bv[q4 * 16 + i][j]     = hv0[i];
                Bv[q4 * 16 + 8 + i][j] = hv1[i];
            }
        }
        __syncthreads();

        // ---- score GEMM: warp computes 16 x 64 (fp16) ----
        float s[8][4] = {};
#pragma unroll
        for (int ks = 0; ks < 4; ks++) {
            const int koff = ks * 16 + kb * 2;
            uint32_t bq[8][2];
#pragma unroll
            for (int nt = 0; nt < 8; nt++) {
                bq[nt][0] = *(const uint32_t*)&Bk[nt * 8 + r][koff];
                bq[nt][1] = *(const uint32_t*)&Bk[nt * 8 + r][koff + 8];
            }
#pragma unroll
            for (int nt = 0; nt < 8; nt++)
                mma16(s[nt], aq[ks], bq[nt]);
        }

        // ---- epilogue: pos gather + mask + scale ----
#pragma unroll
        for (int nt = 0; nt < 8; nt++) {
            int jjb = j0 + nt * 8 + 2 * kb;
#pragma unroll
            for (int cc = 0; cc < 2; cc++) {
                int jj = jjb + cc;
                s[nt][cc]     = (jj > row0 + PSQ)     ? -1e30f
                              : (s[nt][cc]     + pos_val(Pm, h, Lr, jj))     * SCALE;
                s[nt][2 + cc] = (jj > row0 + 8 + PSQ) ? -1e30f
                              : (s[nt][2 + cc] + pos_val(Pm, h, Lr + 8, jj)) * SCALE;
            }
        }

        // ---- online softmax update (rows quad-local) ----
        float tm0 = -3.0e38f, tm1 = -3.0e38f;
#pragma unroll
        for (int nt = 0; nt < 8; nt++) {
            tm0 = fmaxf(tm0, fmaxf(s[nt][0], s[nt][1]));
            tm1 = fmaxf(tm1, fmaxf(s[nt][2], s[nt][3]));
        }
        tm0 = fmaxf(tm0, __shfl_xor_sync(0xffffffffu, tm0, 1));
        tm0 = fmaxf(tm0, __shfl_xor_sync(0xffffffffu, tm0, 2));
        tm1 = fmaxf(tm1, __shfl_xor_sync(0xffffffffu, tm1, 1));
        tm1 = fmaxf(tm1, __shfl_xor_sync(0xffffffffu, tm1, 2));
        float mn0 = fmaxf(m0, tm0), mn1 = fmaxf(m1, tm1);
        float f0 = __expf(m0 - mn0), f1 = __expf(m1 - mn1);

        float ps0 = 0.f, ps1 = 0.f;
#pragma unroll
        for (int nt = 0; nt < 8; nt++) {
            s[nt][0] = __expf(s[nt][0] - mn0);
            s[nt][1] = __expf(s[nt][1] - mn0);
            s[nt][2] = __expf(s[nt][2] - mn1);
            s[nt][3] = __expf(s[nt][3] - mn1);
            ps0 += s[nt][0] + s[nt][1];
            ps1 += s[nt][2] + s[nt][3];
        }
        ps0 += __shfl_xor_sync(0xffffffffu, ps0, 1);
        ps0 += __shfl_xor_sync(0xffffffffu, ps0, 2);
        ps1 += __shfl_xor_sync(0xffffffffu, ps1, 1);
        ps1 += __shfl_xor_sync(0xffffffffu, ps1, 2);
        l0 = l0 * f0 + ps0;
        l1 = l1 * f1 + ps1;
        m0 = mn0; m1 = mn1;

#pragma unroll
        for (int nt = 0; nt < 8; nt++) {
            acc_o[nt][0] *= f0; acc_o[nt][1] *= f0;
            acc_o[nt][2] *= f1; acc_o[nt][3] *= f1;
        }

        // ---- probs -> SMEM (half2 pairs, row-major [row][j], warp-private) ----
#pragma unroll
        for (int nt = 0; nt < 8; nt++) {
            int jl = nt * 8 + 2 * kb;
            *(__half2*)&Sq[wm + r][jl]     = __floats2half2_rn(s[nt][0], s[nt][1]);
            *(__half2*)&Sq[wm + r + 8][jl] = __floats2half2_rn(s[nt][2], s[nt][3]);
        }
        __syncwarp();

        // ---- O += probs @ V (fp16) ----
#pragma unroll
        for (int ks = 0; ks < 4; ks++) {
            const int koff = ks * 16 + kb * 2;
            uint32_t a[4];
            a[0] = *(const uint32_t*)&Sq[wm + r][koff];
            a[1] = *(const uint32_t*)&Sq[wm + r + 8][koff];
            a[2] = *(const uint32_t*)&Sq[wm + r][koff + 8];
            a[3] = *(const uint32_t*)&Sq[wm + r + 8][koff + 8];
            uint32_t bq[8][2];
#pragma unroll
            for (int nt = 0; nt < 8; nt++) {
                bq[nt][0] = *(const uint32_t*)&Bv[nt * 8 + r][koff];
                bq[nt][1] = *(const uint32_t*)&Bv[nt * 8 + r][koff + 8];
            }
#pragma unroll
            for (int nt = 0; nt < 8; nt++)
                mma16(acc_o[nt], a, bq[nt]);
        }
        __syncthreads();   // protect Bk/Bv/Sq before next tile
    }

    // ---- normalize and write ao (half) ----
    float inv0 = 1.0f / l0, inv1 = 1.0f / l1;
#pragma unroll
    for (int nt = 0; nt < 8; nt++) {
        int c0 = nt * 8 + 2 * kb;
        __half* o0 = ao + (size_t)(b * CSQ + row0) * HD + h * HDIM + c0;
        *(__half2*)o0            = __floats2half2_rn(acc_o[nt][0] * inv0, acc_o[nt][1] * inv0);
        *(__half2*)(o0 + 8 * HD) = __floats2half2_rn(acc_o[nt][2] * inv1, acc_o[nt][3] * inv1);
    }
}

// ---------------------------------------------------------------------------
// Launch. Inputs: input_, pos_embs, memory, u, v, W_kv, W_q, W_p, W_out, mask.
// ---------------------------------------------------------------------------
extern "C" void kernel_launch(void* const* d_in, const int* in_sizes, int n_in,
                              void* d_out, int out_size)
{
    const float* input_ = (const float*)d_in[0];
    const float* pos    = (const float*)d_in[1];
    const float* memory = (const float*)d_in[2];
    const float* u      = (const float*)d_in[3];
    const float* v      = (const float*)d_in[4];
    const float* W_kv   = (const float*)d_in[5];
    const float* W_q    = (const float*)d_in[6];
    const float* W_p    = (const float*)d_in[7];
    const float* W_out  = (const float*)d_in[8];
    float* out = (float*)d_out;

    float *Pb;
    __half *qvh, *quh, *kvh, *ph, *aoh;
    __half *hin, *hmem, *hpos, *hWkv, *hWq, *hWp, *hWout;
    cudaGetSymbolAddress((void**)&Pb,   g_P);
    cudaGetSymbolAddress((void**)&qvh,  h_qv);
    cudaGetSymbolAddress((void**)&quh,  h_qu);
    cudaGetSymbolAddress((void**)&kvh,  h_kvh);
    cudaGetSymbolAddress((void**)&ph,   h_ph);
    cudaGetSymbolAddress((void**)&aoh,  h_aoh);
    cudaGetSymbolAddress((void**)&hin,  h_in);
    cudaGetSymbolAddress((void**)&hmem, h_mem);
    cudaGetSymbolAddress((void**)&hpos, h_pos);
    cudaGetSymbolAddress((void**)&hWkv, h_Wkv_t);
    cudaGetSymbolAddress((void**)&hWq,  h_Wq_t);
    cudaGetSymbolAddress((void**)&hWp,  h_Wp_t);
    cudaGetSymbolAddress((void**)&hWout, h_Wout_t);

    cudaFuncSetAttribute(gemm_fp16<0,0>, cudaFuncAttributeMaxDynamicSharedMemorySize, GEMMH_SMEM);
    cudaFuncSetAttribute(gemm_fp16<0,1>, cudaFuncAttributeMaxDynamicSharedMemorySize, GEMMH_SMEM);
    cudaFuncSetAttribute(gemm_fp16<0,2>, cudaFuncAttributeMaxDynamicSharedMemorySize, GEMMH_SMEM);
    cudaFuncSetAttribute(gemm_fp16<1,1>, cudaFuncAttributeMaxDynamicSharedMemorySize, GEMMH_SMEM);
    cudaFuncSetAttribute(attn_fused_fp16, cudaFuncAttributeMaxDynamicSharedMemorySize, ATT_SMEM);

    // ---- one-time conversions ----
    auto cvt = [&](const float* src, __half* dst, size_t n) {
        int n4 = (int)(n / 4);
        cvt_f2h<<<(n4 + 255) / 256, 256>>>(src, dst, n4);
    };
    cvt(input_, hin,  (size_t)BSZ * CSQ * DIN);
    cvt(memory, hmem, (size_t)BSZ * PSQ * DIN);
    cvt(pos,    hpos, (size_t)TT * DIN);
    transpose_f2h<<<dim3(HD / 32,     DIN / 32), 256>>>(W_q,   hWq,   DIN, HD);
    transpose_f2h<<<dim3(2 * HD / 32, DIN / 32), 256>>>(W_kv,  hWkv,  DIN, 2 * HD);
    transpose_f2h<<<dim3(HD / 32,     DIN / 32), 256>>>(W_p,   hWp,   DIN, HD);
    transpose_f2h<<<dim3(DIN / 32,    HD / 32),  256>>>(W_out, hWout, HD,  DIN);

    dim3 thr(128);

    // q-GEMM -> qv = half(q+v), qu = half(q+u)
    gemm_fp16<0,2><<<dim3(HD / 128, LQG / 128), thr, GEMMH_SMEM>>>(
        hin, nullptr, hWq, nullptr, qvh, quh, v, u, LQG, HD, DIN);
    // kv = concat(memory, input_) @ W_kv -> half
    gemm_fp16<1,1><<<dim3(2 * HD / 128, (BSZ * TT) / 128), thr, GEMMH_SMEM>>>(
        hmem, hin, hWkv, nullptr, kvh, nullptr, nullptr, nullptr, BSZ * TT, 2 * HD, DIN);
    // p = pos_embs @ W_p -> half
    gemm_fp16<0,1><<<dim3(HD / 128, TT / 128), thr, GEMMH_SMEM>>>(
        hpos, nullptr, hWp, nullptr, ph, nullptr, nullptr, nullptr, TT, HD, DIN);
    // P[h] = qv @ p^T per head (fp16 HMMA, fp32 out)
    pos_gemm_fp16<<<dim3(TT / 128, LQG / 128, NH), thr>>>(qvh, ph, Pb);
    // fused attention (fp16 HMMA)
    attn_fused_fp16<<<dim3(CSQ / 128, BSZ * NH), 256, ATT_SMEM>>>(quh, kvh, Pb, aoh);
    // out = ao @ W_out (fp32 store)
    gemm_fp16<0,0><<<dim3(DIN / 128, LQG / 128), thr, GEMMH_SMEM>>>(
        aoh, nullptr, hWout, out, nullptr, nullptr, nullptr, nullptr, LQG, DIN, HD);
}